// round 2
// baseline (speedup 1.0000x reference)
#include <cuda_runtime.h>
#include <math.h>

#define B_  2
#define S_  2048
#define D_  1024
#define H_  16
#define DEPTH_ 64
#define MROWS (B_*S_)          // 4096
#define OUT_ELEMS  ((size_t)B_*S_*D_)            // 4194304
#define ATTN_ELEMS ((size_t)B_*H_*S_*S_)         // 134217728

// ---- static device scratch (allocation-free rule) ----
__device__ float g_qh[B_*H_*S_*DEPTH_];   // 16 MB each
__device__ float g_kh[B_*H_*S_*DEPTH_];
__device__ float g_vh[B_*H_*S_*DEPTH_];
__device__ float g_pre[B_*S_*D_];
__device__ float g_attn_fallback[1];

// ============================================================
// Projection GEMM (unchanged from R1 — already ~82% of fp32 ceiling)
// ============================================================
__global__ void proj_kernel(const float* __restrict__ X, const float* __restrict__ W,
                            const float* __restrict__ bias, float* __restrict__ out,
                            int headed)
{
    __shared__ float As[16][65];
    __shared__ float Bs[16][64];
    const int tx = threadIdx.x, ty = threadIdx.y;
    const int tid = ty*16 + tx;
    const int row0 = blockIdx.y * 64;
    const int col0 = blockIdx.x * 64;

    float acc[4][4] = {};

    for (int k0 = 0; k0 < 1024; k0 += 16) {
        #pragma unroll
        for (int t = 0; t < 4; ++t) {
            int idx = tid + 256*t;
            int r  = idx >> 4;
            int kk = idx & 15;
            As[kk][r] = X[(size_t)(row0 + r)*1024 + k0 + kk];
        }
        #pragma unroll
        for (int t = 0; t < 4; ++t) {
            int idx = tid + 256*t;
            int kk = idx >> 6;
            int c  = idx & 63;
            Bs[kk][c] = W[(size_t)(k0 + kk)*1024 + col0 + c];
        }
        __syncthreads();
        #pragma unroll
        for (int kk = 0; kk < 16; ++kk) {
            float a[4], b[4];
            #pragma unroll
            for (int i = 0; i < 4; ++i) a[i] = As[kk][ty + 16*i];
            #pragma unroll
            for (int j = 0; j < 4; ++j) b[j] = Bs[kk][tx + 16*j];
            #pragma unroll
            for (int i = 0; i < 4; ++i)
                #pragma unroll
                for (int j = 0; j < 4; ++j)
                    acc[i][j] += a[i]*b[j];
        }
        __syncthreads();
    }

    #pragma unroll
    for (int i = 0; i < 4; ++i) {
        int row = row0 + ty + 16*i;
        #pragma unroll
        for (int j = 0; j < 4; ++j) {
            int col = col0 + tx + 16*j;
            float v = acc[i][j] + bias[col];
            if (headed) {
                int b = row >> 11;
                int s = row & 2047;
                int h = col >> 6;
                int d = col & 63;
                out[(((size_t)(b*H_ + h))*S_ + s)*DEPTH_ + d] = v;
            } else {
                out[(size_t)row*D_ + col] = v;
            }
        }
    }
}

// ============================================================
// Fused attention: logits + online softmax stats + normalize +
// attn write + attn@V, one block per (bh, q-block of 64 rows).
// Upper-triangle blocks are written as exact zeros (softmax of
// -1e17-masked entries underflows to 0 in fp32, matching ref).
// ============================================================
__global__ void attn_fused_kernel(const float* __restrict__ mask, float* __restrict__ attn)
{
    const int bh   = blockIdx.y;
    const int b    = bh >> 4;
    const int h    = bh & 15;
    const int qblk = gridDim.x - 1 - blockIdx.x;   // long blocks launch first
    const int q0   = qblk * 64;
    const int tx = threadIdx.x, ty = threadIdx.y;
    const int tid = ty*16 + tx;

    __shared__ float QPs[64][68];   // Q tile in phase A, P tile in phase B
    __shared__ float KVs[64][68];   // K tile in phase A, V tile in phase B

    const float* Q = g_qh + (size_t)bh*S_*DEPTH_;
    const float* K = g_kh + (size_t)bh*S_*DEPTH_;
    const float* V = g_vh + (size_t)bh*S_*DEPTH_;
    float* A = attn + (size_t)bh*S_*S_;

    // load Q tile [row][d], coalesced float4
    #pragma unroll
    for (int u = 0; u < 4; ++u) {
        int idx = tid + 256*u;           // 0..1023
        int r = idx >> 4, qd = (idx & 15)*4;
        *(float4*)&QPs[r][qd] = *(const float4*)&Q[(size_t)(q0+r)*DEPTH_ + qd];
    }

    float mrun[4], srun[4];
    #pragma unroll
    for (int i = 0; i < 4; ++i) { mrun[i] = -INFINITY; srun[i] = 0.f; }

    const int ntiles = qblk + 1;
    const float scale = 0.125f;

    // ---------------- Phase A: logits + online stats ----------------
    for (int t = 0; t < ntiles; ++t) {
        const int k0 = t*64;
        __syncthreads();
        #pragma unroll
        for (int u = 0; u < 4; ++u) {
            int idx = tid + 256*u;
            int r = idx >> 4, qd = (idx & 15)*4;
            *(float4*)&KVs[r][qd] = *(const float4*)&K[(size_t)(k0+r)*DEPTH_ + qd];
        }
        __syncthreads();

        float acc[4][4] = {};
        #pragma unroll
        for (int d = 0; d < 64; d += 4) {
            float4 a4[4], b4[4];
            #pragma unroll
            for (int i = 0; i < 4; ++i) a4[i] = *(float4*)&QPs[ty + 16*i][d];
            #pragma unroll
            for (int j = 0; j < 4; ++j) b4[j] = *(float4*)&KVs[tx + 16*j][d];
            #pragma unroll
            for (int i = 0; i < 4; ++i)
                #pragma unroll
                for (int j = 0; j < 4; ++j)
                    acc[i][j] += a4[i].x*b4[j].x + a4[i].y*b4[j].y
                               + a4[i].z*b4[j].z + a4[i].w*b4[j].w;
        }

        // mask / causal penalties
        float mk[4];
        #pragma unroll
        for (int j = 0; j < 4; ++j)
            mk[j] = mask[(size_t)b*S_ + k0 + tx + 16*j];

        float x[4][4];
        const bool diag = (t == ntiles - 1);
        #pragma unroll
        for (int i = 0; i < 4; ++i) {
            int qr = q0 + ty + 16*i;
            #pragma unroll
            for (int j = 0; j < 4; ++j) {
                int kc = k0 + tx + 16*j;
                float causal = (diag && kc > qr) ? 1.0f : 0.0f;
                float m = fmaxf(mk[j], causal);
                x[i][j] = acc[i][j]*scale + m * (-1e17f);
            }
        }

        // write raw logits (coalesced scalar stores)
        #pragma unroll
        for (int i = 0; i < 4; ++i) {
            size_t rb = (size_t)(q0 + ty + 16*i)*S_ + k0 + tx;
            #pragma unroll
            for (int j = 0; j < 4; ++j)
                A[rb + 16*j] = x[i][j];
        }

        // online max/sum update (reduce over the 16 tx lanes sharing ty)
        #pragma unroll
        for (int i = 0; i < 4; ++i) {
            float tm = fmaxf(fmaxf(x[i][0], x[i][1]), fmaxf(x[i][2], x[i][3]));
            #pragma unroll
            for (int o = 8; o > 0; o >>= 1)
                tm = fmaxf(tm, __shfl_xor_sync(0xffffffffu, tm, o));
            float mnew = fmaxf(mrun[i], tm);
            float se = __expf(x[i][0]-mnew) + __expf(x[i][1]-mnew)
                     + __expf(x[i][2]-mnew) + __expf(x[i][3]-mnew);
            #pragma unroll
            for (int o = 8; o > 0; o >>= 1)
                se += __shfl_xor_sync(0xffffffffu, se, o);
            srun[i] = srun[i]*__expf(mrun[i]-mnew) + se;
            mrun[i] = mnew;
        }
    }

    float inv[4];
    #pragma unroll
    for (int i = 0; i < 4; ++i) inv[i] = 1.0f / srun[i];

    // ---------------- zero the fully-masked upper-triangle ----------------
    {
        const int zstart = q0 + 64;
        if (zstart < S_) {
            const int nz = S_ - zstart;            // multiple of 64
            const int perRow = nz >> 2;            // float4 per row
            const float4 z4 = make_float4(0.f, 0.f, 0.f, 0.f);
            for (int idx = tid; idx < 64*perRow; idx += 256) {
                int r = idx / perRow;
                int c = (idx - r*perRow) << 2;
                *(float4*)&A[(size_t)(q0 + r)*S_ + zstart + c] = z4;
            }
        }
    }

    // ---------------- Phase B: normalize + write attn + attn@V ----------------
    float acc2[4][4] = {};
    for (int t = 0; t < ntiles; ++t) {
        const int k0 = t*64;
        __syncthreads();
        // V tile
        #pragma unroll
        for (int u = 0; u < 4; ++u) {
            int idx = tid + 256*u;
            int r = idx >> 4, qd = (idx & 15)*4;
            *(float4*)&KVs[r][qd] = *(const float4*)&V[(size_t)(k0+r)*DEPTH_ + qd];
        }
        // read back own raw logits, normalize, write final attn, stage P in smem
        #pragma unroll
        for (int i = 0; i < 4; ++i) {
            size_t rb = (size_t)(q0 + ty + 16*i)*S_ + k0 + tx;
            #pragma unroll
            for (int j = 0; j < 4; ++j) {
                float p = __expf(A[rb + 16*j] - mrun[i]) * inv[i];
                A[rb + 16*j] = p;
                QPs[ty + 16*i][tx + 16*j] = p;
            }
        }
        __syncthreads();

        // acc2[i][j] += sum_k P[row_i][k] * V[k][col_j]
        #pragma unroll
        for (int kk = 0; kk < 64; kk += 4) {
            float4 a4[4];
            #pragma unroll
            for (int i = 0; i < 4; ++i) a4[i] = *(float4*)&QPs[ty + 16*i][kk];
            float bv[4][4];
            #pragma unroll
            for (int u = 0; u < 4; ++u)
                #pragma unroll
                for (int j = 0; j < 4; ++j)
                    bv[u][j] = KVs[kk + u][tx + 16*j];
            #pragma unroll
            for (int i = 0; i < 4; ++i)
                #pragma unroll
                for (int j = 0; j < 4; ++j)
                    acc2[i][j] += a4[i].x*bv[0][j] + a4[i].y*bv[1][j]
                                + a4[i].z*bv[2][j] + a4[i].w*bv[3][j];
        }
    }

    // epilogue: write to g_pre in (B,S,D) layout
    #pragma unroll
    for (int i = 0; i < 4; ++i) {
        int s = q0 + ty + 16*i;
        #pragma unroll
        for (int j = 0; j < 4; ++j) {
            int d = tx + 16*j;
            g_pre[((size_t)b*S_ + s)*D_ + h*DEPTH_ + d] = acc2[i][j];
        }
    }
}

// ============================================================
extern "C" void kernel_launch(void* const* d_in, const int* in_sizes, int n_in,
                              void* d_out, int out_size)
{
    (void)in_sizes; (void)n_in;
    const float* v    = (const float*)d_in[0];
    const float* k    = (const float*)d_in[1];
    const float* q    = (const float*)d_in[2];
    const float* mask = (const float*)d_in[3];
    const float* Wq   = (const float*)d_in[4];
    const float* bq   = (const float*)d_in[5];
    const float* Wk   = (const float*)d_in[6];
    const float* bk   = (const float*)d_in[7];
    const float* Wv   = (const float*)d_in[8];
    const float* bv   = (const float*)d_in[9];
    const float* Wo   = (const float*)d_in[10];
    const float* bo   = (const float*)d_in[11];

    float* out = (float*)d_out;

    float *qh, *kh, *vh, *pre;
    cudaGetSymbolAddress((void**)&qh, g_qh);
    cudaGetSymbolAddress((void**)&kh, g_kh);
    cudaGetSymbolAddress((void**)&vh, g_vh);
    cudaGetSymbolAddress((void**)&pre, g_pre);

    float* attn;
    if ((size_t)out_size >= OUT_ELEMS + ATTN_ELEMS) {
        attn = out + OUT_ELEMS;
    } else {
        cudaGetSymbolAddress((void**)&attn, g_attn_fallback);
    }

    dim3 tb(16, 16);

    dim3 gproj(D_/64, MROWS/64);   // (16, 64)
    proj_kernel<<<gproj, tb>>>(q, Wq, bq, qh, 1);
    proj_kernel<<<gproj, tb>>>(k, Wk, bk, kh, 1);
    proj_kernel<<<gproj, tb>>>(v, Wv, bv, vh, 1);

    dim3 gattn(S_/64, B_*H_);      // (32, 32)
    attn_fused_kernel<<<gattn, tb>>>(mask, attn);

    proj_kernel<<<gproj, tb>>>(pre, Wo, bo, out, 0);
}

// round 4
// speedup vs baseline: 2.3094x; 2.3094x over previous
#include <cuda_runtime.h>
#include <cuda_bf16.h>
#include <math.h>
#include <stdint.h>

#define B_  2
#define S_  2048
#define D_  1024
#define H_  16
#define DEPTH_ 64
#define MROWS (B_*S_)          // 4096
#define KDIM 1024
#define OUT_ELEMS  ((size_t)B_*S_*D_)            // 4194304
#define ATTN_ELEMS ((size_t)B_*H_*S_*S_)         // 134217728

// ---- static device scratch (allocation-free rule) ----
__device__ float g_qh[B_*H_*S_*DEPTH_];
__device__ float g_kh[B_*H_*S_*DEPTH_];
__device__ float g_vh[B_*H_*S_*DEPTH_];
__device__ float g_pre[B_*S_*D_];
__device__ float g_attn_fallback[1];
__device__ __align__(256) __nv_bfloat16 g_xhi[MROWS*KDIM];   // 8MB
__device__ __align__(256) __nv_bfloat16 g_xlo[MROWS*KDIM];
__device__ __align__(256) __nv_bfloat16 g_wthi[KDIM*KDIM];   // W^T [n][k]
__device__ __align__(256) __nv_bfloat16 g_wtlo[KDIM*KDIM];

// ============================================================
// HMMA helpers (plain sm_103-compatible: mma.sync + ldmatrix)
// ============================================================
__device__ __forceinline__ uint32_t lds_addr(const void* p) {
    return (uint32_t)__cvta_generic_to_shared(p);
}

#define LDSM4(r, addr) \
    asm volatile("ldmatrix.sync.aligned.m8n8.x4.shared.b16 {%0,%1,%2,%3}, [%4];" \
        : "=r"((r)[0]), "=r"((r)[1]), "=r"((r)[2]), "=r"((r)[3]) : "r"(addr))

#define MMA16816(c, a, b0, b1) \
    asm volatile("mma.sync.aligned.m16n8k16.row.col.f32.bf16.bf16.f32 " \
        "{%0,%1,%2,%3}, {%4,%5,%6,%7}, {%8,%9}, {%0,%1,%2,%3};" \
        : "+f"((c)[0]), "+f"((c)[1]), "+f"((c)[2]), "+f"((c)[3]) \
        : "r"((a)[0]), "r"((a)[1]), "r"((a)[2]), "r"((a)[3]), "r"(b0), "r"(b1))

// ============================================================
// Split fp32 -> bf16 hi/lo
// ============================================================
__global__ void split_kernel(const float4* __restrict__ x,
                             uint2* __restrict__ hi, uint2* __restrict__ lo, int n4)
{
    int i = blockIdx.x*256 + threadIdx.x;
    if (i >= n4) return;
    float4 v = x[i];
    __nv_bfloat16 h0 = __float2bfloat16(v.x), h1 = __float2bfloat16(v.y);
    __nv_bfloat16 h2 = __float2bfloat16(v.z), h3 = __float2bfloat16(v.w);
    __nv_bfloat16 l0 = __float2bfloat16(v.x - __bfloat162float(h0));
    __nv_bfloat16 l1 = __float2bfloat16(v.y - __bfloat162float(h1));
    __nv_bfloat16 l2 = __float2bfloat16(v.z - __bfloat162float(h2));
    __nv_bfloat16 l3 = __float2bfloat16(v.w - __bfloat162float(h3));
    union { __nv_bfloat16 h[4]; uint2 u; } ph, pl;
    ph.h[0]=h0; ph.h[1]=h1; ph.h[2]=h2; ph.h[3]=h3;
    pl.h[0]=l0; pl.h[1]=l1; pl.h[2]=l2; pl.h[3]=l3;
    hi[i] = ph.u;
    lo[i] = pl.u;
}

// ============================================================
// W [k][n] fp32 -> W^T hi/lo bf16 [n][k]
// ============================================================
__global__ void wsplit_kernel(const float* __restrict__ W,
                              __nv_bfloat16* __restrict__ thi,
                              __nv_bfloat16* __restrict__ tlo)
{
    __shared__ float ts[32][33];
    const int k0 = blockIdx.x*32, n0 = blockIdx.y*32;
    const int tx = threadIdx.x, ty = threadIdx.y;
    #pragma unroll
    for (int u = 0; u < 4; ++u)
        ts[ty + 8*u][tx] = W[(size_t)(k0 + ty + 8*u)*KDIM + n0 + tx];
    __syncthreads();
    #pragma unroll
    for (int u = 0; u < 4; ++u) {
        float v = ts[tx][ty + 8*u];
        __nv_bfloat16 h = __float2bfloat16(v);
        __nv_bfloat16 l = __float2bfloat16(v - __bfloat162float(h));
        size_t idx = (size_t)(n0 + ty + 8*u)*KDIM + k0 + tx;
        thi[idx] = h;
        tlo[idx] = l;
    }
}

// ============================================================
// HMMA split-bf16 GEMM: C = X @ W + bias
// A = Xhi/Xlo [M][K] bf16, B = W^T hi/lo [N][K] bf16.
// Block 128x128, BK=32, 8 warps (warp tile 32x64).
// 3 passes: Ahi*Bhi + Ahi*Blo + Alo*Bhi (fp32 accum).
// ============================================================
#define PADE 40   // bf16 elements per smem row (80 bytes)

__global__ void __launch_bounds__(256)
gemm_hmma(const __nv_bfloat16* __restrict__ Ahi,
          const __nv_bfloat16* __restrict__ Alo,
          const __nv_bfloat16* __restrict__ Bhi,
          const __nv_bfloat16* __restrict__ Blo,
          const float* __restrict__ bias,
          float* __restrict__ out, int headed)
{
    __shared__ __nv_bfloat16 As_hi[128*PADE];
    __shared__ __nv_bfloat16 As_lo[128*PADE];
    __shared__ __nv_bfloat16 Bs_hi[128*PADE];
    __shared__ __nv_bfloat16 Bs_lo[128*PADE];

    const int tid = threadIdx.x;
    const int wid = tid >> 5, lane = tid & 31;
    const int wy = wid & 3;      // M direction: 4 warps x 32 rows
    const int wx = wid >> 2;     // N direction: 2 warps x 64 cols
    const int m0 = blockIdx.y * 128;
    const int n0 = blockIdx.x * 128;

    float acc[2][8][4];
    #pragma unroll
    for (int mi = 0; mi < 2; ++mi)
        #pragma unroll
        for (int ni = 0; ni < 8; ++ni)
            #pragma unroll
            for (int c = 0; c < 4; ++c) acc[mi][ni][c] = 0.f;

    for (int kt = 0; kt < KDIM/32; ++kt) {
        __syncthreads();
        // load 128x32 tiles (each thread: 2 x uint4 per tile)
        #pragma unroll
        for (int u = 0; u < 2; ++u) {
            int idx = tid + 256*u;        // 0..511
            int r = idx >> 2, c = idx & 3;
            size_t ga = (size_t)(m0 + r)*KDIM + kt*32 + c*8;
            size_t gb = (size_t)(n0 + r)*KDIM + kt*32 + c*8;
            int so = r*PADE + c*8;
            *(uint4*)&As_hi[so] = *(const uint4*)&Ahi[ga];
            *(uint4*)&As_lo[so] = *(const uint4*)&Alo[ga];
            *(uint4*)&Bs_hi[so] = *(const uint4*)&Bhi[gb];
            *(uint4*)&Bs_lo[so] = *(const uint4*)&Blo[gb];
        }
        __syncthreads();

        #pragma unroll
        for (int ks = 0; ks < 2; ++ks) {
            uint32_t ahi[2][4], alo[2][4], bhi[4][4], blo[4][4];
            // A fragments: rows wy*32 + mi*16 + (lane%16), k = ks*16 + (lane/16)*8
            {
                int koff = ks*16 + (lane >> 4)*8;
                int r = wy*32 + (lane & 15);
                LDSM4(ahi[0], lds_addr(&As_hi[r*PADE + koff]));
                LDSM4(ahi[1], lds_addr(&As_hi[(r+16)*PADE + koff]));
                LDSM4(alo[0], lds_addr(&As_lo[r*PADE + koff]));
                LDSM4(alo[1], lds_addr(&As_lo[(r+16)*PADE + koff]));
            }
            // B fragments: each x4 covers two n8 tiles
            {
                int nl = (lane & 7) + ((lane >> 4) << 3);
                int kc = ks*16 + ((lane >> 3) & 1)*8;
                #pragma unroll
                for (int p = 0; p < 4; ++p) {
                    int nr = wx*64 + p*16 + nl;
                    LDSM4(bhi[p], lds_addr(&Bs_hi[nr*PADE + kc]));
                    LDSM4(blo[p], lds_addr(&Bs_lo[nr*PADE + kc]));
                }
            }
            #pragma unroll
            for (int mi = 0; mi < 2; ++mi) {
                #pragma unroll
                for (int p = 0; p < 4; ++p) {
                    MMA16816(acc[mi][2*p],   ahi[mi], bhi[p][0], bhi[p][1]);
                    MMA16816(acc[mi][2*p+1], ahi[mi], bhi[p][2], bhi[p][3]);
                    MMA16816(acc[mi][2*p],   ahi[mi], blo[p][0], blo[p][1]);
                    MMA16816(acc[mi][2*p+1], ahi[mi], blo[p][2], blo[p][3]);
                    MMA16816(acc[mi][2*p],   alo[mi], bhi[p][0], bhi[p][1]);
                    MMA16816(acc[mi][2*p+1], alo[mi], bhi[p][2], bhi[p][3]);
                }
            }
        }
    }

    // epilogue with bias; fragment c: rows l/4 (+8), cols (l%4)*2 (+1)
    const int lr = lane >> 2, lc = (lane & 3)*2;
    #pragma unroll
    for (int mi = 0; mi < 2; ++mi) {
        #pragma unroll
        for (int ni = 0; ni < 8; ++ni) {
            int col = n0 + wx*64 + ni*8 + lc;
            float b0 = bias[col], b1 = bias[col+1];
            #pragma unroll
            for (int half = 0; half < 2; ++half) {
                int row = m0 + wy*32 + mi*16 + lr + half*8;
                float v0 = acc[mi][ni][half*2]   + b0;
                float v1 = acc[mi][ni][half*2+1] + b1;
                if (headed) {
                    int b = row >> 11, s = row & 2047;
                    int h = col >> 6, d = col & 63;
                    float* p = &g_qh[0]; (void)p;
                    out[(((size_t)(b*H_ + h))*S_ + s)*DEPTH_ + d]     = v0;
                    out[(((size_t)(b*H_ + h))*S_ + s)*DEPTH_ + d + 1] = v1;
                } else {
                    float2* p = (float2*)&out[(size_t)row*D_ + col];
                    *p = make_float2(v0, v1);
                }
            }
        }
    }
}

// ============================================================
// Logits (R1, measured 321us)
// ============================================================
__global__ void logits_kernel(const float* __restrict__ mask, float* __restrict__ attn)
{
    const int bh = blockIdx.z;
    const int b  = bh / H_;
    const int q0 = blockIdx.y * 64;
    const int k0 = blockIdx.x * 64;
    const int tx = threadIdx.x, ty = threadIdx.y;
    const int tid = ty*16 + tx;
    const float scale = 0.125f;

    float* arow = attn + ((size_t)bh*S_)*S_;

    if (k0 >= q0 + 64) {
        #pragma unroll
        for (int i = 0; i < 4; ++i) {
            int qr = q0 + ty + 16*i;
            #pragma unroll
            for (int j = 0; j < 4; ++j) {
                int kc = k0 + tx + 16*j;
                float m = fmaxf(mask[(size_t)b*S_ + kc], 1.0f);
                arow[(size_t)qr*S_ + kc] = m * (-1e17f);
            }
        }
        return;
    }

    __shared__ float Qs[64][65];
    __shared__ float Ks[64][65];
    const float* Q = g_qh + (size_t)bh*S_*DEPTH_;
    const float* K = g_kh + (size_t)bh*S_*DEPTH_;

    #pragma unroll
    for (int t = 0; t < 16; ++t) {
        int idx = tid + 256*t;
        int r = idx >> 6;
        int d = idx & 63;
        Qs[d][r] = Q[(size_t)(q0 + r)*DEPTH_ + d];
        Ks[d][r] = K[(size_t)(k0 + r)*DEPTH_ + d];
    }
    __syncthreads();

    float acc[4][4] = {};
    #pragma unroll
    for (int d = 0; d < 64; ++d) {
        float a[4], b_[4];
        #pragma unroll
        for (int i = 0; i < 4; ++i) a[i]  = Qs[d][ty + 16*i];
        #pragma unroll
        for (int j = 0; j < 4; ++j) b_[j] = Ks[d][tx + 16*j];
        #pragma unroll
        for (int i = 0; i < 4; ++i)
            #pragma unroll
            for (int j = 0; j < 4; ++j)
                acc[i][j] += a[i]*b_[j];
    }

    #pragma unroll
    for (int i = 0; i < 4; ++i) {
        int qr = q0 + ty + 16*i;
        #pragma unroll
        for (int j = 0; j < 4; ++j) {
            int kc = k0 + tx + 16*j;
            float causal = (kc > qr) ? 1.0f : 0.0f;
            float m = fmaxf(mask[(size_t)b*S_ + kc], causal);
            arow[(size_t)qr*S_ + kc] = acc[i][j]*scale + m * (-1e17f);
        }
    }
}

// ============================================================
// Softmax (R1)
// ============================================================
__global__ void softmax_kernel(float* __restrict__ attn)
{
    const size_t row = blockIdx.x;
    float* p = attn + row * S_;
    const int tid = threadIdx.x;

    __shared__ float red[32];

    float lmax = -INFINITY;
    for (int i = tid; i < S_; i += 256) lmax = fmaxf(lmax, p[i]);
    #pragma unroll
    for (int o = 16; o > 0; o >>= 1) lmax = fmaxf(lmax, __shfl_xor_sync(0xffffffffu, lmax, o));
    if ((tid & 31) == 0) red[tid >> 5] = lmax;
    __syncthreads();
    if (tid < 32) {
        float v = (tid < 8) ? red[tid] : -INFINITY;
        #pragma unroll
        for (int o = 4; o > 0; o >>= 1) v = fmaxf(v, __shfl_xor_sync(0xffffffffu, v, o));
        if (tid == 0) red[0] = v;
    }
    __syncthreads();
    float rowmax = red[0];
    __syncthreads();

    float lsum = 0.0f;
    for (int i = tid; i < S_; i += 256) {
        float e = __expf(p[i] - rowmax);
        p[i] = e;
        lsum += e;
    }
    #pragma unroll
    for (int o = 16; o > 0; o >>= 1) lsum += __shfl_xor_sync(0xffffffffu, lsum, o);
    if ((tid & 31) == 0) red[tid >> 5] = lsum;
    __syncthreads();
    if (tid < 32) {
        float v = (tid < 8) ? red[tid] : 0.0f;
        #pragma unroll
        for (int o = 4; o > 0; o >>= 1) v += __shfl_xor_sync(0xffffffffu, v, o);
        if (tid == 0) red[0] = v;
    }
    __syncthreads();
    float inv = 1.0f / red[0];

    for (int i = tid; i < S_; i += 256) p[i] *= inv;
}

// ============================================================
// AV (R1)
// ============================================================
__global__ void av_kernel(const float* __restrict__ attn)
{
    const int bh = blockIdx.y;
    const int q0 = blockIdx.x * 64;
    const int b = bh / H_, h = bh % H_;
    const int tx = threadIdx.x, ty = threadIdx.y;
    const int tid = ty*16 + tx;

    __shared__ float As[64][65];
    __shared__ float Vs[64][65];

    const float* A = attn + ((size_t)bh*S_)*S_;
    const float* V = g_vh + (size_t)bh*S_*DEPTH_;

    float acc[4][4] = {};

    for (int k0 = 0; k0 <= q0; k0 += 64) {
        #pragma unroll
        for (int t = 0; t < 16; ++t) {
            int idx = tid + 256*t;
            int r = idx >> 6;
            int c = idx & 63;
            As[r][c] = A[(size_t)(q0 + r)*S_ + k0 + c];
            Vs[r][c] = V[(size_t)(k0 + r)*DEPTH_ + c];
        }
        __syncthreads();
        #pragma unroll
        for (int c = 0; c < 64; ++c) {
            float a[4], b_[4];
            #pragma unroll
            for (int i = 0; i < 4; ++i) a[i]  = As[ty + 16*i][c];
            #pragma unroll
            for (int j = 0; j < 4; ++j) b_[j] = Vs[c][tx + 16*j];
            #pragma unroll
            for (int i = 0; i < 4; ++i)
                #pragma unroll
                for (int j = 0; j < 4; ++j)
                    acc[i][j] += a[i]*b_[j];
        }
        __syncthreads();
    }

    #pragma unroll
    for (int i = 0; i < 4; ++i) {
        int s = q0 + ty + 16*i;
        #pragma unroll
        for (int j = 0; j < 4; ++j) {
            int d = tx + 16*j;
            g_pre[((size_t)b*S_ + s)*D_ + h*DEPTH_ + d] = acc[i][j];
        }
    }
}

// ============================================================
extern "C" void kernel_launch(void* const* d_in, const int* in_sizes, int n_in,
                              void* d_out, int out_size)
{
    (void)in_sizes; (void)n_in;
    const float* v    = (const float*)d_in[0];
    const float* k    = (const float*)d_in[1];
    const float* q    = (const float*)d_in[2];
    const float* mask = (const float*)d_in[3];
    const float* Wq   = (const float*)d_in[4];
    const float* bq   = (const float*)d_in[5];
    const float* Wk   = (const float*)d_in[6];
    const float* bk   = (const float*)d_in[7];
    const float* Wv   = (const float*)d_in[8];
    const float* bv   = (const float*)d_in[9];
    const float* Wo   = (const float*)d_in[10];
    const float* bo   = (const float*)d_in[11];

    float* out = (float*)d_out;

    float *qh, *kh, *vh, *pre;
    cudaGetSymbolAddress((void**)&qh, g_qh);
    cudaGetSymbolAddress((void**)&kh, g_kh);
    cudaGetSymbolAddress((void**)&vh, g_vh);
    cudaGetSymbolAddress((void**)&pre, g_pre);
    __nv_bfloat16 *xhi, *xlo, *wthi, *wtlo;
    cudaGetSymbolAddress((void**)&xhi, g_xhi);
    cudaGetSymbolAddress((void**)&xlo, g_xlo);
    cudaGetSymbolAddress((void**)&wthi, g_wthi);
    cudaGetSymbolAddress((void**)&wtlo, g_wtlo);

    float* attn;
    if ((size_t)out_size >= OUT_ELEMS + ATTN_ELEMS) {
        attn = out + OUT_ELEMS;
    } else {
        cudaGetSymbolAddress((void**)&attn, g_attn_fallback);
    }

    const int n4 = MROWS*KDIM/4;
    dim3 gsplit((n4 + 255)/256);
    dim3 gwt(32, 32), twt(32, 8);
    dim3 ggemm(KDIM/128, MROWS/128);   // (8, 32)

    // Q projection
    split_kernel<<<gsplit, 256>>>((const float4*)q, (uint2*)xhi, (uint2*)xlo, n4);
    wsplit_kernel<<<gwt, twt>>>(Wq, wthi, wtlo);
    gemm_hmma<<<ggemm, 256>>>(xhi, xlo, wthi, wtlo, bq, qh, 1);
    // K projection
    split_kernel<<<gsplit, 256>>>((const float4*)k, (uint2*)xhi, (uint2*)xlo, n4);
    wsplit_kernel<<<gwt, twt>>>(Wk, wthi, wtlo);
    gemm_hmma<<<ggemm, 256>>>(xhi, xlo, wthi, wtlo, bk, kh, 1);
    // V projection
    split_kernel<<<gsplit, 256>>>((const float4*)v, (uint2*)xhi, (uint2*)xlo, n4);
    wsplit_kernel<<<gwt, twt>>>(Wv, wthi, wtlo);
    gemm_hmma<<<ggemm, 256>>>(xhi, xlo, wthi, wtlo, bv, vh, 1);

    // attention
    dim3 tb(16, 16);
    dim3 glog(S_/64, S_/64, B_*H_);
    logits_kernel<<<glog, tb>>>(mask, attn);
    softmax_kernel<<<B_*H_*S_, 256>>>(attn);
    dim3 gav(S_/64, B_*H_);
    av_kernel<<<gav, tb>>>(attn);

    // output projection
    split_kernel<<<gsplit, 256>>>((const float4*)pre, (uint2*)xhi, (uint2*)xlo, n4);
    wsplit_kernel<<<gwt, twt>>>(Wo, wthi, wtlo);
    gemm_hmma<<<ggemm, 256>>>(xhi, xlo, wthi, wtlo, bo, out, 0);
}